// round 16
// baseline (speedup 1.0000x reference)
#include <cuda_runtime.h>
#include <math_constants.h>

#define NQ 6
#define DM 128
#define SEQ 2048
#define CHUNK 16
#define BATCH 128
#define NCHUNK (SEQ / CHUNK)      // 128
#define NROWS (BATCH * NCHUNK)    // 16384
#define K2B (NROWS / 16)          // 1024 blocks, 16 rows each

typedef unsigned long long ull;

// Scratch (device globals; no allocation allowed)
__device__ float g_params[NROWS * 128];
__device__ float g_part[K2B * 128];
__device__ float g_pden[K2B];
__device__ float g_cw1[32], g_cb1[32];

__device__ __forceinline__ float tanh_fast(float x) {
    float y; asm("tanh.approx.f32 %0, %1;" : "=f"(y) : "f"(x)); return y;
}
__device__ __forceinline__ ull pack2(float lo, float hi) {
    ull r; asm("mov.b64 %0, {%1, %2};" : "=l"(r) : "f"(lo), "f"(hi)); return r;
}
__device__ __forceinline__ void fma2(ull& d, ull a, ull b) {
    asm("fma.rn.f32x2 %0, %1, %2, %3;" : "=l"(d) : "l"(a), "l"(b), "l"(d));
}
__device__ __forceinline__ float2 unpack2(ull v) {
    float2 f; asm("mov.b64 {%0, %1}, %2;" : "=f"(f.x), "=f"(f.y) : "l"(v)); return f;
}
#define SHX(v, m) __shfl_xor_sync(0xffffffffu, (v), (m))

// ===========================================================================
// Kernel 0: batch-invariant folded-LN constants
// ===========================================================================
__global__ __launch_bounds__(256) void k0(
    const float* __restrict__ ca1_w,
    const float* __restrict__ ln1_g, const float* __restrict__ ln1_b)
{
    __shared__ float rw[256], rb[256];
    int t = threadIdx.x;
    int j = t & 31, seg = t >> 5;
    float pw = 0.f, pb = 0.f;
#pragma unroll 4
    for (int dd = seg * 16; dd < seg * 16 + 16; dd++) {
        float wv = ca1_w[dd * 32 + j];
        pw = fmaf(wv, ln1_g[dd], pw);
        pb = fmaf(wv, ln1_b[dd], pb);
    }
    rw[t] = pw; rb[t] = pb;
    __syncthreads();
    if (t < 32) {
        float sw = 0.f, sb = 0.f;
#pragma unroll
        for (int s = 0; s < 8; s++) { sw += rw[s * 32 + t]; sb += rb[s * 32 + t]; }
        g_cw1[t] = sw; g_cb1[t] = sb;
    }
}

// ===========================================================================
// Kernel 1: conv1d + (folded LN) + chunk attention + pp projection (fused)
//           + ep projection
// one block = 8 chunks (128 seq positions) of one batch row; 256 threads
// ===========================================================================
struct K1Smem {
    float sx[4][132];
    float ht[128 * 130];
    float w1[128 * 32];
    float lng[128], lnb[128];
    float b1[32], w2[32];
    float scp[4 * 128];
    float cw1[32], cb1[32];
    float wgt[128];
    float chC[16];
    float mv[128], rv[128];
    float summ[8 * 128];
    float epw[768];
    float epb[8];
};

__global__ __launch_bounds__(256) void k1(
    const float* __restrict__ x, const float* __restrict__ conv_w, const float* __restrict__ conv_b,
    const float* __restrict__ ln1_g, const float* __restrict__ ln1_b,
    const float* __restrict__ ca1_w, const float* __restrict__ ca1_b,
    const float* __restrict__ ca2_w, const float* __restrict__ ca2_b,
    const float* __restrict__ pp_w, const float* __restrict__ pp_b,
    const float* __restrict__ ep_w, const float* __restrict__ ep_b)
{
    extern __shared__ char smem_raw[];
    K1Smem& S = *reinterpret_cast<K1Smem*>(smem_raw);

    const int bid = blockIdx.x;
    const int b = bid >> 4;
    const int g = bid & 15;
    const int s_base = g * 128;
    const int t = threadIdx.x;

    if (t < 128) { S.lng[t] = ln1_g[t]; S.lnb[t] = ln1_b[t]; }
    for (int i = t; i < 4096; i += 256) S.w1[i] = ca1_w[i] * __ldg(&ln1_g[i >> 5]);
    if (t < 32) {
        S.b1[t] = ca1_b[t]; S.w2[t] = ca2_w[t];
        S.cw1[t] = g_cw1[t]; S.cb1[t] = g_cb1[t];
    }
    for (int i = t; i < 768; i += 256) S.epw[i] = ep_w[i];
    if (t < 6) S.epb[t] = ep_b[t];
    for (int i = t; i < 4 * 130; i += 256) {
        int c = i / 130, k = i % 130;
        int s = s_base - 1 + k;
        float v = 0.f;
        if (s >= 0 && s < SEQ) v = x[(b * 4 + c) * SEQ + s];
        S.sx[c][k] = v;
    }
    __syncthreads();

    const int d = t & 127;
    const int half = t >> 7;

    // ---- conv (packed 2 positions per step), direct-ldg weights ----
    {
        const int p0c = half * 64;
        ull wp[12];
#pragma unroll
        for (int k = 0; k < 12; k++) { float wv = __ldg(&conv_w[d * 12 + k]); wp[k] = pack2(wv, wv); }
        float bv = conv_b[d];
        ull bias2 = pack2(bv, bv);
        float xs0[4], xs1[4];
#pragma unroll
        for (int c = 0; c < 4; c++) { xs0[c] = S.sx[c][p0c]; xs1[c] = S.sx[c][p0c + 1]; }
#pragma unroll 4
        for (int p = p0c; p < p0c + 64; p += 2) {
            ull a2 = bias2;
#pragma unroll
            for (int c = 0; c < 4; c++) {
                float x2 = S.sx[c][p + 2], x3 = S.sx[c][p + 3];
                fma2(a2, pack2(xs0[c], xs1[c]), wp[c * 3 + 0]);
                fma2(a2, pack2(xs1[c], x2),     wp[c * 3 + 1]);
                fma2(a2, pack2(x2, x3),         wp[c * 3 + 2]);
                xs0[c] = x2; xs1[c] = x3;
            }
            *reinterpret_cast<ull*>(&S.ht[d * 130 + p]) = a2;
        }
    }
    __syncthreads();

    // ---- LN stats partials ----
    {
        int pos = t & 127;
        float s = 0.f, ss = 0.f;
#pragma unroll 4
        for (int dd = half * 64; dd < half * 64 + 64; dd++) {
            float v = S.ht[dd * 130 + pos];
            s += v; ss = fmaf(v, v, ss);
        }
        S.scp[t] = s; S.scp[256 + t] = ss;
    }
    __syncthreads();
    if (t < 128) {
        float s = S.scp[t] + S.scp[128 + t];
        float ss = S.scp[256 + t] + S.scp[384 + t];
        float m = s * (1.f / 128.f);
        float var = ss * (1.f / 128.f) - m * m;
        S.mv[t] = m; S.rv[t] = rsqrtf(var + 1e-5f);
    }
    __syncthreads();

    // ---- scores on RAW h with folded LN affine ----
    {
        const int pp = t & 63;
        const int p0 = 2 * pp;
        const int jq = t >> 6;
        const int j0 = 8 * jq;
        ull acc2[2][4];
#pragma unroll
        for (int r = 0; r < 2; r++)
#pragma unroll
            for (int c = 0; c < 4; c++) acc2[r][c] = 0ull;
        for (int dd = 0; dd < 128; dd++) {
            float2 h2 = *reinterpret_cast<const float2*>(&S.ht[dd * 130 + p0]);
            ull hx = pack2(h2.x, h2.x), hy = pack2(h2.y, h2.y);
            ulonglong2 wpa = *reinterpret_cast<const ulonglong2*>(&S.w1[dd * 32 + j0]);
            ulonglong2 wpb = *reinterpret_cast<const ulonglong2*>(&S.w1[dd * 32 + j0 + 4]);
            fma2(acc2[0][0], hx, wpa.x); fma2(acc2[0][1], hx, wpa.y);
            fma2(acc2[0][2], hx, wpb.x); fma2(acc2[0][3], hx, wpb.y);
            fma2(acc2[1][0], hy, wpa.x); fma2(acc2[1][1], hy, wpa.y);
            fma2(acc2[1][2], hy, wpb.x); fma2(acc2[1][3], hy, wpb.y);
        }
#pragma unroll
        for (int r = 0; r < 2; r++) {
            float rvp = S.rv[p0 + r];
            float rm = rvp * S.mv[p0 + r];
            float sp = 0.f;
#pragma unroll
            for (int c = 0; c < 4; c++) {
                float2 f = unpack2(acc2[r][c]);
                int j = j0 + 2 * c;
                float v0 = rvp * f.x - rm * S.cw1[j]     + S.cb1[j]     + S.b1[j];
                float v1 = rvp * f.y - rm * S.cw1[j + 1] + S.cb1[j + 1] + S.b1[j + 1];
                sp = fmaf(tanh_fast(v0), S.w2[j],     sp);
                sp = fmaf(tanh_fast(v1), S.w2[j + 1], sp);
            }
            S.scp[jq * 128 + p0 + r] = sp;
        }
    }
    __syncthreads();

    // ---- combine + softmax per chunk ----
    if (t < 128) {
        float v = S.scp[t] + S.scp[128 + t] + S.scp[256 + t] + S.scp[384 + t] + ca2_b[0];
        float m = v;
#pragma unroll
        for (int o = 8; o; o >>= 1) m = fmaxf(m, __shfl_xor_sync(0xffffffffu, m, o, 16));
        float e = __expf(v - m);
        float sm = e;
#pragma unroll
        for (int o = 8; o; o >>= 1) sm += __shfl_xor_sync(0xffffffffu, sm, o, 16);
        float wv = e / sm;
        float aval = wv * S.rv[t];
        S.wgt[t] = aval;
        float cc = aval * S.mv[t];
#pragma unroll
        for (int o = 8; o; o >>= 1) cc += __shfl_xor_sync(0xffffffffu, cc, o, 16);
        if ((t & 15) == 0) S.chC[t >> 4] = cc;
    }
    __syncthreads();

    // ---- weighted sums on RAW h with folded LN (smem only) ----
    {
        float gd = S.lng[d], bd = S.lnb[d];
        for (int c = 4 * half; c < 4 * half + 4; c++) {
            float a = 0.f;
#pragma unroll
            for (int p = 0; p < 16; p++)
                a = fmaf(S.wgt[c * 16 + p], S.ht[d * 130 + c * 16 + p], a);
            S.summ[c * 128 + d] = fmaf(gd, a - S.chC[c], bd);
        }
    }
    __syncthreads();

    // ---- FUSED pp projection: thread = (col j<120, row-group rg of 4) ----
    {
        int j = t & 127, rg = t >> 7;
        if (j < 120) {
            const float* s0 = &S.summ[(rg * 4 + 0) * 128];
            const float* s1 = &S.summ[(rg * 4 + 1) * 128];
            const float* s2 = &S.summ[(rg * 4 + 2) * 128];
            const float* s3 = &S.summ[(rg * 4 + 3) * 128];
            float a0 = 0.f, a1 = 0.f, a2 = 0.f, a3 = 0.f;
#pragma unroll 4
            for (int dd = 0; dd < 128; dd++) {
                float wv = __ldg(&pp_w[dd * 120 + j]);
                a0 = fmaf(s0[dd], wv, a0);
                a1 = fmaf(s1[dd], wv, a1);
                a2 = fmaf(s2[dd], wv, a2);
                a3 = fmaf(s3[dd], wv, a3);
            }
            float bj = pp_b[j];
            int gr = b * 128 + g * 8 + rg * 4;
            g_params[(gr + 0) * 128 + j] = a0 + bj;
            g_params[(gr + 1) * 128 + j] = a1 + bj;
            g_params[(gr + 2) * 128 + j] = a2 + bj;
            g_params[(gr + 3) * 128 + j] = a3 + bj;
        }
    }

    // ---- ep projection partials (reads S.summ, writes S.scp: no sync needed
    //      vs pp phase — disjoint read/write sets) ----
    if (t < 192) {
        int r = t / 24, rem = t % 24;
        int j = rem >> 2, qq = rem & 3;
        float a = (qq == 0) ? S.epb[j] : 0.f;
#pragma unroll 4
        for (int dd = qq * 32; dd < qq * 32 + 32; dd++)
            a = fmaf(S.summ[r * 128 + dd], S.epw[dd * 6 + j], a);
        S.scp[t] = a;
    }
    __syncthreads();
    if (t < 48) {
        int r = t / 6, j = t % 6;
        int base = r * 24 + j * 4;
        float a = S.scp[base] + S.scp[base + 1] + S.scp[base + 2] + S.scp[base + 3];
        g_params[(b * 128 + g * 8 + r) * 128 + 120 + j] =
            tanhf(a) * 3.14159265358979323846f;
    }
}

// ===========================================================================
// Kernel 2 (round-13/15 proven version): TWO rows per warp, coalesced s_par
// staging (float4). 16 lanes/row; 4 complex amps per lane.
// ===========================================================================
#define TBL_STRIDE 208

__global__ __launch_bounds__(256) void k2(
    const float* __restrict__ op_w, const float* __restrict__ op_b,
    const float* __restrict__ ln2_g, const float* __restrict__ ln2_b,
    const float* __restrict__ sa1_w, const float* __restrict__ sa1_b,
    const float* __restrict__ sa2_w, const float* __restrict__ sa2_b)
{
    const int tt = threadIdx.x;
    const int w = tt >> 5;
    const int lane = tt & 31;
    const int grp = lane >> 4;
    const int hl = lane & 15;
    const int rowid = w * 2 + grp;

    __shared__ __align__(16) float s_par[16][128];
    __shared__ __align__(16) float s_tbl[16][TBL_STRIDE];
    __shared__ float w1s[128 * 32];
    __shared__ float b1s[32], w2s[32];
    __shared__ float s_ews[16];
    __shared__ float s_half[2][128];

    for (int i = tt; i < 4096; i += 256) w1s[i] = sa1_w[i];
    if (tt < 32) { b1s[tt] = sa1_b[tt]; w2s[tt] = sa2_w[tt]; }
    {
        const float4* gp4 = reinterpret_cast<const float4*>(g_params + (size_t)blockIdx.x * 16 * 128);
        float4* sp4 = reinterpret_cast<float4*>(&s_par[0][0]);
#pragma unroll
        for (int i = tt; i < 512; i += 256) sp4[i] = gp4[i];
    }
    __syncthreads();

    const float* par = s_par[rowid];
    float* T = s_tbl[rowid];

    for (int gg = hl; gg < 24; gg += 16) {
        int a = gg / 6, i = gg % 6;
        const float* base = par + (a >> 1) * 60 + (a & 1) * 30;
        float sa, ca; __sincosf(0.5f * base[3 * i],     &sa, &ca);
        float sb, cb; __sincosf(0.5f * base[3 * i + 1], &sb, &cb);
        float sg, cg; __sincosf(0.5f * base[3 * i + 2], &sg, &cg);
        float ur = cb * ca, ui = sb * sa;
        float wr = sb * ca, wi = -cb * sa;
        T[4 * gg + 0] = cg * ur + sg * ui;
        T[4 * gg + 1] = cg * ui - sg * ur;
        T[4 * gg + 2] = sg * wi - cg * wr;
        T[4 * gg + 3] = cg * wi + sg * wr;
    }
    for (int gg = hl; gg < 48; gg += 16) {
        int a = gg / 12, j = gg % 12;
        const float* base = par + (a >> 1) * 60 + (a & 1) * 30;
        float s, c; __sincosf(0.5f * base[18 + j], &s, &c);
        T[96 + 2 * gg] = c; T[97 + 2 * gg] = s;
    }
    if (hl < 6) {
        float s, c; __sincosf(0.5f * par[120 + hl], &s, &c);
        T[192 + 2 * hl] = c; T[193 + 2 * hl] = s;
    }
    __syncwarp();

    float ar[4], ai[4];
    {
        float base = 1.f;
#pragma unroll
        for (int q = 0; q < 4; q++) {
            float c = T[192 + 2 * q], s = T[193 + 2 * q];
            base *= ((hl >> (3 - q)) & 1) ? s : c;
        }
        float c4 = T[200], s4 = T[201], c5 = T[202], s5 = T[203];
        ar[0] = base * c4 * c5; ar[1] = base * c4 * s5;
        ar[2] = base * s4 * c5; ar[3] = base * s4 * s5;
        ai[0] = ai[1] = ai[2] = ai[3] = 0.f;
    }

#pragma unroll
    for (int a = 0; a < 4; a++) {
        const float* F = T + a * 24;
        const float* C = T + 96 + a * 24;
#pragma unroll
        for (int i = 0; i < NQ; i++) {
            float4 pq = *reinterpret_cast<const float4*>(&F[4 * i]);
            float Pr = pq.x, Pi = pq.y, Qr = pq.z, Qi = pq.w;
            if (i <= 3) {
                int m = 1 << (3 - i);
                int bit = (hl >> (3 - i)) & 1;
                float lPi = bit ? -Pi : Pi;
                float lQr = bit ? -Qr : Qr;
#pragma unroll
                for (int k = 0; k < 4; k++) {
                    float br = SHX(ar[k], m), bi = SHX(ai[k], m);
                    float nr = Pr * ar[k] - lPi * ai[k] + lQr * br - Qi * bi;
                    float ni = Pr * ai[k] + lPi * ar[k] + lQr * bi + Qi * br;
                    ar[k] = nr; ai[k] = ni;
                }
            } else {
                int px0 = 0, py0 = (i == 4) ? 2 : 1;
                int px1 = (i == 4) ? 1 : 2, py1 = 3;
#pragma unroll
                for (int pp2 = 0; pp2 < 2; pp2++) {
                    int px = pp2 ? px1 : px0, py = pp2 ? py1 : py0;
                    float xr = ar[px], xi = ai[px], yr = ar[py], yi = ai[py];
                    float nxr = Pr * xr - Pi * xi + Qr * yr - Qi * yi;
                    float nxi = Pr * xi + Pi * xr + Qr * yi + Qi * yr;
                    float nyr = -Qr * xr - Qi * xi + Pr * yr + Pi * yi;
                    float nyi = -Qr * xi + Qi * xr + Pr * yi - Pi * yr;
                    ar[px] = nxr; ai[px] = nxi; ar[py] = nyr; ai[py] = nyi;
                }
            }
        }
#pragma unroll
        for (int j = 0; j < 12; j++) {
            float2 cs = *reinterpret_cast<const float2*>(&C[2 * j]);
            float c = cs.x, s = cs.y;
            int cq = (j < 6) ? j : (11 - j);
            int tq = (j < 6) ? ((j + 1) % 6) : ((cq + 5) % 6);
            if (cq <= 3 && tq <= 3) {
                int m = 1 << (3 - tq);
                float br[4], bi[4];
#pragma unroll
                for (int k = 0; k < 4; k++) { br[k] = SHX(ar[k], m); bi[k] = SHX(ai[k], m); }
                if ((hl >> (3 - cq)) & 1) {
#pragma unroll
                    for (int k = 0; k < 4; k++) {
                        float nr = c * ar[k] + s * bi[k];
                        float ni = c * ai[k] - s * br[k];
                        ar[k] = nr; ai[k] = ni;
                    }
                }
            } else if (cq <= 3) {
                if ((hl >> (3 - cq)) & 1) {
                    int px0 = 0, py0 = (tq == 4) ? 2 : 1;
                    int px1 = (tq == 4) ? 1 : 2, py1 = 3;
#pragma unroll
                    for (int pp2 = 0; pp2 < 2; pp2++) {
                        int px = pp2 ? px1 : px0, py = pp2 ? py1 : py0;
                        float xr = ar[px], xi = ai[px], yr = ar[py], yi = ai[py];
                        ar[px] = c * xr + s * yi; ai[px] = c * xi - s * yr;
                        ar[py] = c * yr + s * xi; ai[py] = c * yi - s * xr;
                    }
                }
            } else if (tq <= 3) {
                int m = 1 << (3 - tq);
                int k0 = (cq == 4) ? 2 : 1;
                int k1v = 3;
                float br0 = SHX(ar[k0], m), bi0 = SHX(ai[k0], m);
                float br1 = SHX(ar[k1v], m), bi1 = SHX(ai[k1v], m);
                float nr0 = c * ar[k0] + s * bi0, ni0 = c * ai[k0] - s * br0;
                float nr1 = c * ar[k1v] + s * bi1, ni1 = c * ai[k1v] - s * br1;
                ar[k0] = nr0; ai[k0] = ni0; ar[k1v] = nr1; ai[k1v] = ni1;
            } else {
                int px = (cq == 4) ? 2 : 1, py = 3;
                float xr = ar[px], xi = ai[px], yr = ar[py], yi = ai[py];
                ar[px] = c * xr + s * yi; ai[px] = c * xi - s * yr;
                ar[py] = c * yr + s * xi; ai[py] = c * yi - s * xr;
            }
        }
    }

    float qv[18];
#pragma unroll
    for (int i = 0; i < NQ; i++) {
        float cr, ci, z;
        float n0 = ar[0] * ar[0] + ai[0] * ai[0];
        float n1 = ar[1] * ar[1] + ai[1] * ai[1];
        float n2 = ar[2] * ar[2] + ai[2] * ai[2];
        float n3 = ar[3] * ar[3] + ai[3] * ai[3];
        if (i <= 3) {
            int m = 1 << (3 - i);
            float br[4], bi[4];
#pragma unroll
            for (int k = 0; k < 4; k++) { br[k] = SHX(ar[k], m); bi[k] = SHX(ai[k], m); }
            if (((hl >> (3 - i)) & 1) == 0) {
                cr = ci = 0.f;
#pragma unroll
                for (int k = 0; k < 4; k++) {
                    cr = fmaf(ar[k], br[k], fmaf(ai[k], bi[k], cr));
                    ci = fmaf(ar[k], bi[k], ci) - ai[k] * br[k];
                }
                z = n0 + n1 + n2 + n3;
            } else {
                cr = 0.f; ci = 0.f; z = -(n0 + n1 + n2 + n3);
            }
        } else if (i == 4) {
            cr = ar[0] * ar[2] + ai[0] * ai[2] + ar[1] * ar[3] + ai[1] * ai[3];
            ci = ar[0] * ai[2] - ai[0] * ar[2] + ar[1] * ai[3] - ai[1] * ar[3];
            z  = n0 + n1 - n2 - n3;
        } else {
            cr = ar[0] * ar[1] + ai[0] * ai[1] + ar[2] * ar[3] + ai[2] * ai[3];
            ci = ar[0] * ai[1] - ai[0] * ar[1] + ar[2] * ai[3] - ai[2] * ar[3];
            z  = n0 - n1 + n2 - n3;
        }
#pragma unroll
        for (int o = 8; o; o >>= 1) {
            cr += SHX(cr, o);
            ci += SHX(ci, o);
            z  += SHX(z, o);
        }
        qv[i] = 2.f * cr; qv[6 + i] = 2.f * ci; qv[12 + i] = z;
    }

    float acc[8];
#pragma unroll
    for (int j = 0; j < 8; j++) {
        int dch = hl + 16 * j;
        float a = op_b[dch];
#pragma unroll
        for (int k = 0; k < 18; k++) a = fmaf(qv[k], __ldg(&op_w[k * 128 + dch]), a);
        acc[j] = a;
    }
    float sum = 0.f;
#pragma unroll
    for (int j = 0; j < 8; j++) sum += acc[j];
#pragma unroll
    for (int o = 8; o; o >>= 1) sum += SHX(sum, o);
    float mean = sum * (1.f / 128.f);
    float vs = 0.f;
#pragma unroll
    for (int j = 0; j < 8; j++) { float d0 = acc[j] - mean; vs = fmaf(d0, d0, vs); }
#pragma unroll
    for (int o = 8; o; o >>= 1) vs += SHX(vs, o);
    float rstd = rsqrtf(vs * (1.f / 128.f) + 1e-5f);

    float* cfrow = s_par[rowid];
#pragma unroll
    for (int j = 0; j < 8; j++) {
        int dch = hl + 16 * j;
        float xv = (acc[j] - mean) * rstd * ln2_g[dch] + ln2_b[dch];
        cfrow[dch] = xv / (1.f + __expf(-xv));
    }
    __syncwarp();

    {
        float a0 = b1s[hl], a1 = b1s[hl + 16];
#pragma unroll 4
        for (int dd = 0; dd < 128; dd++) {
            float cf = cfrow[dd];
            a0 = fmaf(cf, w1s[dd * 32 + hl], a0);
            a1 = fmaf(cf, w1s[dd * 32 + hl + 16], a1);
        }
        float v = fmaf(tanh_fast(a0), w2s[hl], tanh_fast(a1) * w2s[hl + 16]);
#pragma unroll
        for (int o = 8; o; o >>= 1) v += SHX(v, o);
        if (hl == 0) s_ews[rowid] = __expf(v + sa2_b[0]);
    }
    __syncthreads();

    {
        int dch = tt & 127, hh = tt >> 7;
        float p = 0.f;
#pragma unroll
        for (int ww = hh * 8; ww < hh * 8 + 8; ww++)
            p = fmaf(s_ews[ww], s_par[ww][dch], p);
        s_half[hh][dch] = p;
    }
    __syncthreads();
    if (tt < 128) {
        g_part[blockIdx.x * 128 + tt] = s_half[0][tt] + s_half[1][tt];
    } else if (tt == 128) {
        float den = 0.f;
#pragma unroll
        for (int ww = 0; ww < 16; ww++) den += s_ews[ww];
        g_pden[blockIdx.x] = den;
    }
}

// ===========================================================================
// Kernel k3: combine 8 partials + classifier
// ===========================================================================
__global__ __launch_bounds__(512) void k3(
    const float* __restrict__ cl1_w, const float* __restrict__ cl1_b,
    const float* __restrict__ cl2_w, const float* __restrict__ cl2_b,
    float* __restrict__ out)
{
    int b = blockIdx.x;
    int t = threadIdx.x;
    __shared__ float rep_s[DM];
    __shared__ float u_part[8][64];
    __shared__ float u_s[64];
    __shared__ float den_s;

    if (t < 128) {
        float acc = 0.f;
#pragma unroll
        for (int i = 0; i < 8; i++)
            acc += g_part[(b * 8 + i) * 128 + t];
        rep_s[t] = acc;
    } else if (t < 160) {
        int lane = t - 128;
        float dv = (lane < 8) ? g_pden[b * 8 + lane] : 0.f;
#pragma unroll
        for (int o = 4; o; o >>= 1) dv += __shfl_xor_sync(0xffffffffu, dv, o, 8);
        if (lane == 0) den_s = dv;
    }
    __syncthreads();
    float dinv = 1.f / den_s;

    {
        int j = t & 63, seg = t >> 6;
        float a = 0.f;
#pragma unroll
        for (int dd = seg * 16; dd < seg * 16 + 16; dd++)
            a = fmaf(rep_s[dd], __ldg(&cl1_w[dd * 64 + j]), a);
        u_part[seg][j] = a;
    }
    __syncthreads();
    if (t < 64) {
        float a = (u_part[0][t] + u_part[1][t] + u_part[2][t] + u_part[3][t]
                 + u_part[4][t] + u_part[5][t] + u_part[6][t] + u_part[7][t]) * dinv
                + cl1_b[t];
        u_s[t] = a / (1.f + __expf(-a));
    }
    __syncthreads();
    if (t < 2) {
        float o = cl2_b[t];
#pragma unroll 8
        for (int j = 0; j < 64; j++) o = fmaf(u_s[j], __ldg(&cl2_w[j * 2 + t]), o);
        out[b * 2 + t] = o;
    }
}

// ===========================================================================
extern "C" void kernel_launch(void* const* d_in, const int* in_sizes, int n_in,
                              void* d_out, int out_size)
{
    const float* x      = (const float*)d_in[0];
    const float* conv_w = (const float*)d_in[1];
    const float* conv_b = (const float*)d_in[2];
    const float* ln1_g  = (const float*)d_in[3];
    const float* ln1_b  = (const float*)d_in[4];
    const float* ca1_w  = (const float*)d_in[5];
    const float* ca1_b  = (const float*)d_in[6];
    const float* ca2_w  = (const float*)d_in[7];
    const float* ca2_b  = (const float*)d_in[8];
    const float* pp_w   = (const float*)d_in[9];
    const float* pp_b   = (const float*)d_in[10];
    const float* ep_w   = (const float*)d_in[11];
    const float* ep_b   = (const float*)d_in[12];
    const float* op_w   = (const float*)d_in[13];
    const float* op_b   = (const float*)d_in[14];
    const float* ln2_g  = (const float*)d_in[15];
    const float* ln2_b  = (const float*)d_in[16];
    const float* sa1_w  = (const float*)d_in[17];
    const float* sa1_b  = (const float*)d_in[18];
    const float* sa2_w  = (const float*)d_in[19];
    const float* sa2_b  = (const float*)d_in[20];
    const float* cl1_w  = (const float*)d_in[21];
    const float* cl1_b  = (const float*)d_in[22];
    const float* cl2_w  = (const float*)d_in[23];
    const float* cl2_b  = (const float*)d_in[24];
    float* out = (float*)d_out;

    cudaFuncSetAttribute(k1, cudaFuncAttributeMaxDynamicSharedMemorySize, (int)sizeof(K1Smem));

    k0<<<1, 256>>>(ca1_w, ln1_g, ln1_b);
    k1<<<BATCH * 16, 256, sizeof(K1Smem)>>>(x, conv_w, conv_b, ln1_g, ln1_b,
                                            ca1_w, ca1_b, ca2_w, ca2_b,
                                            pp_w, pp_b, ep_w, ep_b);
    k2<<<K2B, 256>>>(op_w, op_b, ln2_g, ln2_b, sa1_w, sa1_b, sa2_w, sa2_b);
    k3<<<BATCH, 512>>>(cl1_w, cl1_b, cl2_w, cl2_b, out);
}

// round 17
// speedup vs baseline: 1.0638x; 1.0638x over previous
#include <cuda_runtime.h>
#include <math_constants.h>

#define NQ 6
#define DM 128
#define SEQ 2048
#define CHUNK 16
#define BATCH 128
#define NCHUNK (SEQ / CHUNK)      // 128
#define NROWS (BATCH * NCHUNK)    // 16384
#define K2B (NROWS / 16)          // 1024 blocks, 16 rows each

typedef unsigned long long ull;

// Scratch (device globals; no allocation allowed)
__device__ float g_params[NROWS * 128];
__device__ float g_summ[NROWS * 128];
__device__ float g_part[K2B * 128];
__device__ float g_pden[K2B];
__device__ float g_cw1[32], g_cb1[32];

__device__ __forceinline__ float tanh_fast(float x) {
    float y; asm("tanh.approx.f32 %0, %1;" : "=f"(y) : "f"(x)); return y;
}
__device__ __forceinline__ ull pack2(float lo, float hi) {
    ull r; asm("mov.b64 %0, {%1, %2};" : "=l"(r) : "f"(lo), "f"(hi)); return r;
}
__device__ __forceinline__ void fma2(ull& d, ull a, ull b) {
    asm("fma.rn.f32x2 %0, %1, %2, %3;" : "=l"(d) : "l"(a), "l"(b), "l"(d));
}
__device__ __forceinline__ float2 unpack2(ull v) {
    float2 f; asm("mov.b64 {%0, %1}, %2;" : "=f"(f.x), "=f"(f.y) : "l"(v)); return f;
}
#define SHX(v, m) __shfl_xor_sync(0xffffffffu, (v), (m))

// ===========================================================================
// Kernel 0: batch-invariant folded-LN constants
// ===========================================================================
__global__ __launch_bounds__(256) void k0(
    const float* __restrict__ ca1_w,
    const float* __restrict__ ln1_g, const float* __restrict__ ln1_b)
{
    __shared__ float rw[256], rb[256];
    int t = threadIdx.x;
    int j = t & 31, seg = t >> 5;
    float pw = 0.f, pb = 0.f;
#pragma unroll 4
    for (int dd = seg * 16; dd < seg * 16 + 16; dd++) {
        float wv = ca1_w[dd * 32 + j];
        pw = fmaf(wv, ln1_g[dd], pw);
        pb = fmaf(wv, ln1_b[dd], pb);
    }
    rw[t] = pw; rb[t] = pb;
    __syncthreads();
    if (t < 32) {
        float sw = 0.f, sb = 0.f;
#pragma unroll
        for (int s = 0; s < 8; s++) { sw += rw[s * 32 + t]; sb += rb[s * 32 + t]; }
        g_cw1[t] = sw; g_cb1[t] = sb;
    }
}

// ===========================================================================
// Kernel 1: conv1d + (folded LN) + chunk attention + ep projection
// ===========================================================================
struct K1Smem {
    float sx[4][132];
    float ht[128 * 130];
    float w1[128 * 32];
    float cw[128 * 13];
    float lng[128], lnb[128];
    float b1[32], w2[32];
    float scp[4 * 128];
    float cw1[32], cb1[32];
    float wgt[128];
    float chC[16];
    float mv[128], rv[128];
    float summ[8 * 128];
    float epw[768];
    float epb[8];
};

__global__ __launch_bounds__(256) void k1(
    const float* __restrict__ x, const float* __restrict__ conv_w, const float* __restrict__ conv_b,
    const float* __restrict__ ln1_g, const float* __restrict__ ln1_b,
    const float* __restrict__ ca1_w, const float* __restrict__ ca1_b,
    const float* __restrict__ ca2_w, const float* __restrict__ ca2_b,
    const float* __restrict__ ep_w, const float* __restrict__ ep_b)
{
    extern __shared__ char smem_raw[];
    K1Smem& S = *reinterpret_cast<K1Smem*>(smem_raw);

    const int bid = blockIdx.x;
    const int b = bid >> 4;
    const int g = bid & 15;
    const int s_base = g * 128;
    const int t = threadIdx.x;

    if (t < 128) { S.lng[t] = ln1_g[t]; S.lnb[t] = ln1_b[t]; }
    for (int i = t; i < 4096; i += 256) S.w1[i] = ca1_w[i] * __ldg(&ln1_g[i >> 5]);
    for (int i = t; i < 1536; i += 256) S.cw[(i / 12) * 13 + (i % 12)] = conv_w[i];
    if (t < 32) {
        S.b1[t] = ca1_b[t]; S.w2[t] = ca2_w[t];
        S.cw1[t] = g_cw1[t]; S.cb1[t] = g_cb1[t];
    }
    for (int i = t; i < 768; i += 256) S.epw[i] = ep_w[i];
    if (t < 6) S.epb[t] = ep_b[t];
    for (int i = t; i < 4 * 130; i += 256) {
        int c = i / 130, k = i % 130;
        int s = s_base - 1 + k;
        float v = 0.f;
        if (s >= 0 && s < SEQ) v = x[(b * 4 + c) * SEQ + s];
        S.sx[c][k] = v;
    }
    __syncthreads();

    const int d = t & 127;
    const int half = t >> 7;

    {
        const int p0c = half * 64;
        ull wp[12];
#pragma unroll
        for (int k = 0; k < 12; k++) { float wv = S.cw[d * 13 + k]; wp[k] = pack2(wv, wv); }
        float bv = conv_b[d];
        ull bias2 = pack2(bv, bv);
        float xs0[4], xs1[4];
#pragma unroll
        for (int c = 0; c < 4; c++) { xs0[c] = S.sx[c][p0c]; xs1[c] = S.sx[c][p0c + 1]; }
#pragma unroll 4
        for (int p = p0c; p < p0c + 64; p += 2) {
            ull a2 = bias2;
#pragma unroll
            for (int c = 0; c < 4; c++) {
                float x2 = S.sx[c][p + 2], x3 = S.sx[c][p + 3];
                fma2(a2, pack2(xs0[c], xs1[c]), wp[c * 3 + 0]);
                fma2(a2, pack2(xs1[c], x2),     wp[c * 3 + 1]);
                fma2(a2, pack2(x2, x3),         wp[c * 3 + 2]);
                xs0[c] = x2; xs1[c] = x3;
            }
            *reinterpret_cast<ull*>(&S.ht[d * 130 + p]) = a2;
        }
    }
    __syncthreads();

    {
        int pos = t & 127;
        float s = 0.f, ss = 0.f;
#pragma unroll 4
        for (int dd = half * 64; dd < half * 64 + 64; dd++) {
            float v = S.ht[dd * 130 + pos];
            s += v; ss = fmaf(v, v, ss);
        }
        S.scp[t] = s; S.scp[256 + t] = ss;
    }
    __syncthreads();
    if (t < 128) {
        float s = S.scp[t] + S.scp[128 + t];
        float ss = S.scp[256 + t] + S.scp[384 + t];
        float m = s * (1.f / 128.f);
        float var = ss * (1.f / 128.f) - m * m;
        S.mv[t] = m; S.rv[t] = rsqrtf(var + 1e-5f);
    }
    __syncthreads();

    {
        const int pp = t & 63;
        const int p0 = 2 * pp;
        const int jq = t >> 6;
        const int j0 = 8 * jq;
        ull acc2[2][4];
#pragma unroll
        for (int r = 0; r < 2; r++)
#pragma unroll
            for (int c = 0; c < 4; c++) acc2[r][c] = 0ull;
        for (int dd = 0; dd < 128; dd++) {
            float2 h2 = *reinterpret_cast<const float2*>(&S.ht[dd * 130 + p0]);
            ull hx = pack2(h2.x, h2.x), hy = pack2(h2.y, h2.y);
            ulonglong2 wpa = *reinterpret_cast<const ulonglong2*>(&S.w1[dd * 32 + j0]);
            ulonglong2 wpb = *reinterpret_cast<const ulonglong2*>(&S.w1[dd * 32 + j0 + 4]);
            fma2(acc2[0][0], hx, wpa.x); fma2(acc2[0][1], hx, wpa.y);
            fma2(acc2[0][2], hx, wpb.x); fma2(acc2[0][3], hx, wpb.y);
            fma2(acc2[1][0], hy, wpa.x); fma2(acc2[1][1], hy, wpa.y);
            fma2(acc2[1][2], hy, wpb.x); fma2(acc2[1][3], hy, wpb.y);
        }
#pragma unroll
        for (int r = 0; r < 2; r++) {
            float rvp = S.rv[p0 + r];
            float rm = rvp * S.mv[p0 + r];
            float sp = 0.f;
#pragma unroll
            for (int c = 0; c < 4; c++) {
                float2 f = unpack2(acc2[r][c]);
                int j = j0 + 2 * c;
                float v0 = rvp * f.x - rm * S.cw1[j]     + S.cb1[j]     + S.b1[j];
                float v1 = rvp * f.y - rm * S.cw1[j + 1] + S.cb1[j + 1] + S.b1[j + 1];
                sp = fmaf(tanh_fast(v0), S.w2[j],     sp);
                sp = fmaf(tanh_fast(v1), S.w2[j + 1], sp);
            }
            S.scp[jq * 128 + p0 + r] = sp;
        }
    }
    __syncthreads();

    if (t < 128) {
        float v = S.scp[t] + S.scp[128 + t] + S.scp[256 + t] + S.scp[384 + t] + ca2_b[0];
        float m = v;
#pragma unroll
        for (int o = 8; o; o >>= 1) m = fmaxf(m, __shfl_xor_sync(0xffffffffu, m, o, 16));
        float e = __expf(v - m);
        float sm = e;
#pragma unroll
        for (int o = 8; o; o >>= 1) sm += __shfl_xor_sync(0xffffffffu, sm, o, 16);
        float wv = e / sm;
        float aval = wv * S.rv[t];
        S.wgt[t] = aval;
        float cc = aval * S.mv[t];
#pragma unroll
        for (int o = 8; o; o >>= 1) cc += __shfl_xor_sync(0xffffffffu, cc, o, 16);
        if ((t & 15) == 0) S.chC[t >> 4] = cc;
    }
    __syncthreads();

    {
        float gd = S.lng[d], bd = S.lnb[d];
        for (int c = 4 * half; c < 4 * half + 4; c++) {
            float a = 0.f;
#pragma unroll
            for (int p = 0; p < 16; p++)
                a = fmaf(S.wgt[c * 16 + p], S.ht[d * 130 + c * 16 + p], a);
            float sv = fmaf(gd, a - S.chC[c], bd);
            S.summ[c * 128 + d] = sv;
            g_summ[(b * 128 + g * 8 + c) * 128 + d] = sv;
        }
    }
    __syncthreads();

    if (t < 192) {
        int r = t / 24, rem = t % 24;
        int j = rem >> 2, qq = rem & 3;
        float a = (qq == 0) ? S.epb[j] : 0.f;
#pragma unroll 4
        for (int dd = qq * 32; dd < qq * 32 + 32; dd++)
            a = fmaf(S.summ[r * 128 + dd], S.epw[dd * 6 + j], a);
        S.scp[t] = a;
    }
    __syncthreads();
    if (t < 48) {
        int r = t / 6, j = t % 6;
        int base = r * 24 + j * 4;
        float a = S.scp[base] + S.scp[base + 1] + S.scp[base + 2] + S.scp[base + 3];
        g_params[(b * 128 + g * 8 + r) * 128 + 120 + j] =
            tanhf(a) * 3.14159265358979323846f;
    }
}

// ===========================================================================
// Kernel k_pp: pp projection GEMM  (16384 x 128) @ (128 x 120), f32x2 packed
// ===========================================================================
struct KPSmem {
    float w[128 * 128];
    float s[64 * 129];
};

__global__ __launch_bounds__(256) void k_pp(
    const float* __restrict__ pp_w, const float* __restrict__ pp_b)
{
    extern __shared__ char smem_raw[];
    KPSmem& S = *reinterpret_cast<KPSmem*>(smem_raw);
    const int t = threadIdx.x;
    const int r0 = blockIdx.x * 64;

    for (int i = t; i < 128 * 128; i += 256) S.w[i] = 0.f;
    __syncthreads();
    for (int i = t; i < 128 * 120; i += 256) {
        int dd = i / 120, j = i % 120;
        S.w[dd * 128 + j] = pp_w[i];
    }
    for (int i = t; i < 64 * 128; i += 256) {
        int r = i >> 7, c = i & 127;
        S.s[r * 129 + c] = g_summ[(r0 + r) * 128 + c];
    }
    __syncthreads();

    const int tx = t & 15;
    const int ty = t >> 4;
    ull acc2[4][4];
#pragma unroll
    for (int i = 0; i < 4; i++)
#pragma unroll
        for (int c = 0; c < 4; c++) acc2[i][c] = 0ull;

    for (int dd = 0; dd < 128; dd++) {
        ulonglong2 wpa = *reinterpret_cast<const ulonglong2*>(&S.w[dd * 128 + 8 * tx]);
        ulonglong2 wpb = *reinterpret_cast<const ulonglong2*>(&S.w[dd * 128 + 8 * tx + 4]);
        ull sv2[4];
#pragma unroll
        for (int i = 0; i < 4; i++) {
            float sv = S.s[(4 * ty + i) * 129 + dd];
            sv2[i] = pack2(sv, sv);
        }
#pragma unroll
        for (int i = 0; i < 4; i++) {
            fma2(acc2[i][0], sv2[i], wpa.x);
            fma2(acc2[i][1], sv2[i], wpa.y);
            fma2(acc2[i][2], sv2[i], wpb.x);
            fma2(acc2[i][3], sv2[i], wpb.y);
        }
    }
#pragma unroll
    for (int i = 0; i < 4; i++) {
        int gr = r0 + 4 * ty + i;
#pragma unroll
        for (int c = 0; c < 4; c++) {
            float2 f = unpack2(acc2[i][c]);
            int j = 8 * tx + 2 * c;
            if (j < 120)     g_params[gr * 128 + j]     = f.x + pp_b[j];
            if (j + 1 < 120) g_params[gr * 128 + j + 1] = f.y + pp_b[j + 1];
        }
    }
}

// ===========================================================================
// Kernel 2 (round-15 proven version): TWO rows per warp, coalesced s_par
// staging (float4). 16 lanes/row; 4 complex amps per lane.
// ===========================================================================
#define TBL_STRIDE 208

__global__ __launch_bounds__(256) void k2(
    const float* __restrict__ op_w, const float* __restrict__ op_b,
    const float* __restrict__ ln2_g, const float* __restrict__ ln2_b,
    const float* __restrict__ sa1_w, const float* __restrict__ sa1_b,
    const float* __restrict__ sa2_w, const float* __restrict__ sa2_b)
{
    const int tt = threadIdx.x;
    const int w = tt >> 5;
    const int lane = tt & 31;
    const int grp = lane >> 4;
    const int hl = lane & 15;
    const int rowid = w * 2 + grp;

    __shared__ __align__(16) float s_par[16][128];
    __shared__ __align__(16) float s_tbl[16][TBL_STRIDE];
    __shared__ float w1s[128 * 32];
    __shared__ float b1s[32], w2s[32];
    __shared__ float s_ews[16];
    __shared__ float s_half[2][128];

    for (int i = tt; i < 4096; i += 256) w1s[i] = sa1_w[i];
    if (tt < 32) { b1s[tt] = sa1_b[tt]; w2s[tt] = sa2_w[tt]; }
    {
        const float4* gp4 = reinterpret_cast<const float4*>(g_params + (size_t)blockIdx.x * 16 * 128);
        float4* sp4 = reinterpret_cast<float4*>(&s_par[0][0]);
#pragma unroll
        for (int i = tt; i < 512; i += 256) sp4[i] = gp4[i];
    }
    __syncthreads();

    const float* par = s_par[rowid];
    float* T = s_tbl[rowid];

    for (int gg = hl; gg < 24; gg += 16) {
        int a = gg / 6, i = gg % 6;
        const float* base = par + (a >> 1) * 60 + (a & 1) * 30;
        float sa, ca; __sincosf(0.5f * base[3 * i],     &sa, &ca);
        float sb, cb; __sincosf(0.5f * base[3 * i + 1], &sb, &cb);
        float sg, cg; __sincosf(0.5f * base[3 * i + 2], &sg, &cg);
        float ur = cb * ca, ui = sb * sa;
        float wr = sb * ca, wi = -cb * sa;
        T[4 * gg + 0] = cg * ur + sg * ui;
        T[4 * gg + 1] = cg * ui - sg * ur;
        T[4 * gg + 2] = sg * wi - cg * wr;
        T[4 * gg + 3] = cg * wi + sg * wr;
    }
    for (int gg = hl; gg < 48; gg += 16) {
        int a = gg / 12, j = gg % 12;
        const float* base = par + (a >> 1) * 60 + (a & 1) * 30;
        float s, c; __sincosf(0.5f * base[18 + j], &s, &c);
        T[96 + 2 * gg] = c; T[97 + 2 * gg] = s;
    }
    if (hl < 6) {
        float s, c; __sincosf(0.5f * par[120 + hl], &s, &c);
        T[192 + 2 * hl] = c; T[193 + 2 * hl] = s;
    }
    __syncwarp();

    float ar[4], ai[4];
    {
        float base = 1.f;
#pragma unroll
        for (int q = 0; q < 4; q++) {
            float c = T[192 + 2 * q], s = T[193 + 2 * q];
            base *= ((hl >> (3 - q)) & 1) ? s : c;
        }
        float c4 = T[200], s4 = T[201], c5 = T[202], s5 = T[203];
        ar[0] = base * c4 * c5; ar[1] = base * c4 * s5;
        ar[2] = base * s4 * c5; ar[3] = base * s4 * s5;
        ai[0] = ai[1] = ai[2] = ai[3] = 0.f;
    }

#pragma unroll
    for (int a = 0; a < 4; a++) {
        const float* F = T + a * 24;
        const float* C = T + 96 + a * 24;
#pragma unroll
        for (int i = 0; i < NQ; i++) {
            float4 pq = *reinterpret_cast<const float4*>(&F[4 * i]);
            float Pr = pq.x, Pi = pq.y, Qr = pq.z, Qi = pq.w;
            if (i <= 3) {
                int m = 1 << (3 - i);
                int bit = (hl >> (3 - i)) & 1;
                float lPi = bit ? -Pi : Pi;
                float lQr = bit ? -Qr : Qr;
#pragma unroll
                for (int k = 0; k < 4; k++) {
                    float br = SHX(ar[k], m), bi = SHX(ai[k], m);
                    float nr = Pr * ar[k] - lPi * ai[k] + lQr * br - Qi * bi;
                    float ni = Pr * ai[k] + lPi * ar[k] + lQr * bi + Qi * br;
                    ar[k] = nr; ai[k] = ni;
                }
            } else {
                int px0 = 0, py0 = (i == 4) ? 2 : 1;
                int px1 = (i == 4) ? 1 : 2, py1 = 3;
#pragma unroll
                for (int pp2 = 0; pp2 < 2; pp2++) {
                    int px = pp2 ? px1 : px0, py = pp2 ? py1 : py0;
                    float xr = ar[px], xi = ai[px], yr = ar[py], yi = ai[py];
                    float nxr = Pr * xr - Pi * xi + Qr * yr - Qi * yi;
                    float nxi = Pr * xi + Pi * xr + Qr * yi + Qi * yr;
                    float nyr = -Qr * xr - Qi * xi + Pr * yr + Pi * yi;
                    float nyi = -Qr * xi + Qi * xr + Pr * yi - Pi * yr;
                    ar[px] = nxr; ai[px] = nxi; ar[py] = nyr; ai[py] = nyi;
                }
            }
        }
#pragma unroll
        for (int j = 0; j < 12; j++) {
            float2 cs = *reinterpret_cast<const float2*>(&C[2 * j]);
            float c = cs.x, s = cs.y;
            int cq = (j < 6) ? j : (11 - j);
            int tq = (j < 6) ? ((j + 1) % 6) : ((cq + 5) % 6);
            if (cq <= 3 && tq <= 3) {
                int m = 1 << (3 - tq);
                float br[4], bi[4];
#pragma unroll
                for (int k = 0; k < 4; k++) { br[k] = SHX(ar[k], m); bi[k] = SHX(ai[k], m); }
                if ((hl >> (3 - cq)) & 1) {
#pragma unroll
                    for (int k = 0; k < 4; k++) {
                        float nr = c * ar[k] + s * bi[k];
                        float ni = c * ai[k] - s * br[k];
                        ar[k] = nr; ai[k] = ni;
                    }
                }
            } else if (cq <= 3) {
                if ((hl >> (3 - cq)) & 1) {
                    int px0 = 0, py0 = (tq == 4) ? 2 : 1;
                    int px1 = (tq == 4) ? 1 : 2, py1 = 3;
#pragma unroll
                    for (int pp2 = 0; pp2 < 2; pp2++) {
                        int px = pp2 ? px1 : px0, py = pp2 ? py1 : py0;
                        float xr = ar[px], xi = ai[px], yr = ar[py], yi = ai[py];
                        ar[px] = c * xr + s * yi; ai[px] = c * xi - s * yr;
                        ar[py] = c * yr + s * xi; ai[py] = c * yi - s * xr;
                    }
                }
            } else if (tq <= 3) {
                int m = 1 << (3 - tq);
                int k0 = (cq == 4) ? 2 : 1;
                int k1v = 3;
                float br0 = SHX(ar[k0], m), bi0 = SHX(ai[k0], m);
                float br1 = SHX(ar[k1v], m), bi1 = SHX(ai[k1v], m);
                float nr0 = c * ar[k0] + s * bi0, ni0 = c * ai[k0] - s * br0;
                float nr1 = c * ar[k1v] + s * bi1, ni1 = c * ai[k1v] - s * br1;
                ar[k0] = nr0; ai[k0] = ni0; ar[k1v] = nr1; ai[k1v] = ni1;
            } else {
                int px = (cq == 4) ? 2 : 1, py = 3;
                float xr = ar[px], xi = ai[px], yr = ar[py], yi = ai[py];
                ar[px] = c * xr + s * yi; ai[px] = c * xi - s * yr;
                ar[py] = c * yr + s * xi; ai[py] = c * yi - s * xr;
            }
        }
    }

    float qv[18];
#pragma unroll
    for (int i = 0; i < NQ; i++) {
        float cr, ci, z;
        float n0 = ar[0] * ar[0] + ai[0] * ai[0];
        float n1 = ar[1] * ar[1] + ai[1] * ai[1];
        float n2 = ar[2] * ar[2] + ai[2] * ai[2];
        float n3 = ar[3] * ar[3] + ai[3] * ai[3];
        if (i <= 3) {
            int m = 1 << (3 - i);
            float br[4], bi[4];
#pragma unroll
            for (int k = 0; k < 4; k++) { br[k] = SHX(ar[k], m); bi[k] = SHX(ai[k], m); }
            if (((hl >> (3 - i)) & 1) == 0) {
                cr = ci = 0.f;
#pragma unroll
                for (int k = 0; k < 4; k++) {
                    cr = fmaf(ar[k], br[k], fmaf(ai[k], bi[k], cr));
                    ci = fmaf(ar[k], bi[k], ci) - ai[k] * br[k];
                }
                z = n0 + n1 + n2 + n3;
            } else {
                cr = 0.f; ci = 0.f; z = -(n0 + n1 + n2 + n3);
            }
        } else if (i == 4) {
            cr = ar[0] * ar[2] + ai[0] * ai[2] + ar[1] * ar[3] + ai[1] * ai[3];
            ci = ar[0] * ai[2] - ai[0] * ar[2] + ar[1] * ai[3] - ai[1] * ar[3];
            z  = n0 + n1 - n2 - n3;
        } else {
            cr = ar[0] * ar[1] + ai[0] * ai[1] + ar[2] * ar[3] + ai[2] * ai[3];
            ci = ar[0] * ai[1] - ai[0] * ar[1] + ar[2] * ai[3] - ai[2] * ar[3];
            z  = n0 - n1 + n2 - n3;
        }
#pragma unroll
        for (int o = 8; o; o >>= 1) {
            cr += SHX(cr, o);
            ci += SHX(ci, o);
            z  += SHX(z, o);
        }
        qv[i] = 2.f * cr; qv[6 + i] = 2.f * ci; qv[12 + i] = z;
    }

    float acc[8];
#pragma unroll
    for (int j = 0; j < 8; j++) {
        int dch = hl + 16 * j;
        float a = op_b[dch];
#pragma unroll
        for (int k = 0; k < 18; k++) a = fmaf(qv[k], __ldg(&op_w[k * 128 + dch]), a);
        acc[j] = a;
    }
    float sum = 0.f;
#pragma unroll
    for (int j = 0; j < 8; j++) sum += acc[j];
#pragma unroll
    for (int o = 8; o; o >>= 1) sum += SHX(sum, o);
    float mean = sum * (1.f / 128.f);
    float vs = 0.f;
#pragma unroll
    for (int j = 0; j < 8; j++) { float d0 = acc[j] - mean; vs = fmaf(d0, d0, vs); }
#pragma unroll
    for (int o = 8; o; o >>= 1) vs += SHX(vs, o);
    float rstd = rsqrtf(vs * (1.f / 128.f) + 1e-5f);

    float* cfrow = s_par[rowid];
#pragma unroll
    for (int j = 0; j < 8; j++) {
        int dch = hl + 16 * j;
        float xv = (acc[j] - mean) * rstd * ln2_g[dch] + ln2_b[dch];
        cfrow[dch] = xv / (1.f + __expf(-xv));
    }
    __syncwarp();

    {
        float a0 = b1s[hl], a1 = b1s[hl + 16];
#pragma unroll 4
        for (int dd = 0; dd < 128; dd++) {
            float cf = cfrow[dd];
            a0 = fmaf(cf, w1s[dd * 32 + hl], a0);
            a1 = fmaf(cf, w1s[dd * 32 + hl + 16], a1);
        }
        float v = fmaf(tanh_fast(a0), w2s[hl], tanh_fast(a1) * w2s[hl + 16]);
#pragma unroll
        for (int o = 8; o; o >>= 1) v += SHX(v, o);
        if (hl == 0) s_ews[rowid] = __expf(v + sa2_b[0]);
    }
    __syncthreads();

    {
        int dch = tt & 127, hh = tt >> 7;
        float p = 0.f;
#pragma unroll
        for (int ww = hh * 8; ww < hh * 8 + 8; ww++)
            p = fmaf(s_ews[ww], s_par[ww][dch], p);
        s_half[hh][dch] = p;
    }
    __syncthreads();
    if (tt < 128) {
        g_part[blockIdx.x * 128 + tt] = s_half[0][tt] + s_half[1][tt];
    } else if (tt == 128) {
        float den = 0.f;
#pragma unroll
        for (int ww = 0; ww < 16; ww++) den += s_ews[ww];
        g_pden[blockIdx.x] = den;
    }
}

// ===========================================================================
// Kernel k3: combine 8 partials + classifier
// ===========================================================================
__global__ __launch_bounds__(512) void k3(
    const float* __restrict__ cl1_w, const float* __restrict__ cl1_b,
    const float* __restrict__ cl2_w, const float* __restrict__ cl2_b,
    float* __restrict__ out)
{
    int b = blockIdx.x;
    int t = threadIdx.x;
    __shared__ float rep_s[DM];
    __shared__ float u_part[8][64];
    __shared__ float u_s[64];
    __shared__ float den_s;

    if (t < 128) {
        float acc = 0.f;
#pragma unroll
        for (int i = 0; i < 8; i++)
            acc += g_part[(b * 8 + i) * 128 + t];
        rep_s[t] = acc;
    } else if (t < 160) {
        int lane = t - 128;
        float dv = (lane < 8) ? g_pden[b * 8 + lane] : 0.f;
#pragma unroll
        for (int o = 4; o; o >>= 1) dv += __shfl_xor_sync(0xffffffffu, dv, o, 8);
        if (lane == 0) den_s = dv;
    }
    __syncthreads();
    float dinv = 1.f / den_s;

    {
        int j = t & 63, seg = t >> 6;
        float a = 0.f;
#pragma unroll
        for (int dd = seg * 16; dd < seg * 16 + 16; dd++)
            a = fmaf(rep_s[dd], __ldg(&cl1_w[dd * 64 + j]), a);
        u_part[seg][j] = a;
    }
    __syncthreads();
    if (t < 64) {
        float a = (u_part[0][t] + u_part[1][t] + u_part[2][t] + u_part[3][t]
                 + u_part[4][t] + u_part[5][t] + u_part[6][t] + u_part[7][t]) * dinv
                + cl1_b[t];
        u_s[t] = a / (1.f + __expf(-a));
    }
    __syncthreads();
    if (t < 2) {
        float o = cl2_b[t];
#pragma unroll 8
        for (int j = 0; j < 64; j++) o = fmaf(u_s[j], __ldg(&cl2_w[j * 2 + t]), o);
        out[b * 2 + t] = o;
    }
}

// ===========================================================================
extern "C" void kernel_launch(void* const* d_in, const int* in_sizes, int n_in,
                              void* d_out, int out_size)
{
    const float* x      = (const float*)d_in[0];
    const float* conv_w = (const float*)d_in[1];
    const float* conv_b = (const float*)d_in[2];
    const float* ln1_g  = (const float*)d_in[3];
    const float* ln1_b  = (const float*)d_in[4];
    const float* ca1_w  = (const float*)d_in[5];
    const float* ca1_b  = (const float*)d_in[6];
    const float* ca2_w  = (const float*)d_in[7];
    const float* ca2_b  = (const float*)d_in[8];
    const float* pp_w   = (const float*)d_in[9];
    const float* pp_b   = (const float*)d_in[10];
    const float* ep_w   = (const float*)d_in[11];
    const float* ep_b   = (const float*)d_in[12];
    const float* op_w   = (const float*)d_in[13];
    const float* op_b   = (const float*)d_in[14];
    const float* ln2_g  = (const float*)d_in[15];
    const float* ln2_b  = (const float*)d_in[16];
    const float* sa1_w  = (const float*)d_in[17];
    const float* sa1_b  = (const float*)d_in[18];
    const float* sa2_w  = (const float*)d_in[19];
    const float* sa2_b  = (const float*)d_in[20];
    const float* cl1_w  = (const float*)d_in[21];
    const float* cl1_b  = (const float*)d_in[22];
    const float* cl2_w  = (const float*)d_in[23];
    const float* cl2_b  = (const float*)d_in[24];
    float* out = (float*)d_out;

    cudaFuncSetAttribute(k1, cudaFuncAttributeMaxDynamicSharedMemorySize, (int)sizeof(K1Smem));
    cudaFuncSetAttribute(k_pp, cudaFuncAttributeMaxDynamicSharedMemorySize, (int)sizeof(KPSmem));

    k0<<<1, 256>>>(ca1_w, ln1_g, ln1_b);
    k1<<<BATCH * 16, 256, sizeof(K1Smem)>>>(x, conv_w, conv_b, ln1_g, ln1_b,
                                            ca1_w, ca1_b, ca2_w, ca2_b, ep_w, ep_b);
    k_pp<<<NROWS / 64, 256, sizeof(KPSmem)>>>(pp_w, pp_b);
    k2<<<K2B, 256>>>(op_w, op_b, ln2_g, ln2_b, sa1_w, sa1_b, sa2_w, sa2_b);
    k3<<<BATCH, 512>>>(cl1_w, cl1_b, cl2_w, cl2_b, out);
}